// round 8
// baseline (speedup 1.0000x reference)
#include <cuda_runtime.h>
#include <cuda_bf16.h>
#include <cstdint>

#define N_ROWS   4194304
#define N_DIM    64
#define N_IMG    1024

// scratch accumulators (no allocation allowed; zero-initialized at load,
// invariant: re-zeroed by finalize/zero_counts at the end of every launch)
__device__ float g_sums[N_IMG * N_DIM];
__device__ int   g_counts[N_IMG];

// exactly 4 blocks per SM on 148 SMs -> perfectly even single wave
#define BLOCKS   592
#define THREADS  256
#define WARPS_PER_BLOCK (THREADS / 32)
#define N_WARPS  (BLOCKS * WARPS_PER_BLOCK)      // 4736
#define CHUNK    128
#define N_CHUNKS (N_ROWS / CHUNK)                // 32768

__global__ __launch_bounds__(THREADS, 4)
void main_kernel(const float* __restrict__ x,
                 const int* __restrict__ image_id,
                 float* __restrict__ out) {
    // ---- fused id copy: grid-stride over 1M int4
    {
        int tid = blockIdx.x * blockDim.x + threadIdx.x;
        const int4* src = reinterpret_cast<const int4*>(image_id);
        float4* dst = reinterpret_cast<float4*>(out + N_IMG * N_DIM);
        for (int i = tid; i < N_ROWS / 4; i += BLOCKS * THREADS) {
            int4 v = __ldcs(&src[i]);
            dst[i] = make_float4((float)v.x, (float)v.y, (float)v.z, (float)v.w);
        }
    }

    int gwarp = blockIdx.x * WARPS_PER_BLOCK + (threadIdx.x >> 5);
    int lane  = threadIdx.x & 31;
    int half  = lane >> 4;        // 0: even row of pair, 1: odd row
    int sub   = lane & 15;        // float4 slot (4 dims) within a row

    const float4* __restrict__ x4 = reinterpret_cast<const float4*>(x);
    const float2* __restrict__ x2 = reinterpret_cast<const float2*>(x);

    // chunk-strided work assignment: warp w takes chunks w, w+N_WARPS, ...
    for (int c = gwarp; c < N_CHUNKS; c += N_WARPS) {
        int rc  = c * CHUNK;
        int ida = __ldg(&image_id[rc]);
        int idb = __ldg(&image_id[rc + CHUNK - 1]);

        if (ida == idb) {
            // ---- fast chunk (~97%): uniform segment across 128 rows
            const float4* __restrict__ p =
                x4 + (size_t)(rc + half) * (N_DIM / 4) + sub;
            float4 a0 = make_float4(0.f, 0.f, 0.f, 0.f);
            float4 a1 = make_float4(0.f, 0.f, 0.f, 0.f);
            #pragma unroll 4
            for (int i = 0; i < CHUNK / 4; ++i) {
                float4 v0 = __ldcs(p + (size_t)(2 * i + 0) * (2 * N_DIM / 4));
                float4 v1 = __ldcs(p + (size_t)(2 * i + 1) * (2 * N_DIM / 4));
                a0.x += v0.x; a0.y += v0.y; a0.z += v0.z; a0.w += v0.w;
                a1.x += v1.x; a1.y += v1.y; a1.z += v1.z; a1.w += v1.w;
            }
            float4 t = make_float4(a0.x + a1.x, a0.y + a1.y,
                                   a0.z + a1.z, a0.w + a1.w);
            t.x += __shfl_down_sync(0xffffffff, t.x, 16);
            t.y += __shfl_down_sync(0xffffffff, t.y, 16);
            t.z += __shfl_down_sync(0xffffffff, t.z, 16);
            t.w += __shfl_down_sync(0xffffffff, t.w, 16);
            if (half == 0) {
                float* s = &g_sums[ida * N_DIM + sub * 4];
                atomicAdd(s + 0, t.x);
                atomicAdd(s + 1, t.y);
                atomicAdd(s + 2, t.z);
                atomicAdd(s + 3, t.w);
            }
            if (lane == 0) atomicAdd(&g_counts[ida], CHUNK);
        } else {
            // ---- slow chunk (~3%): boundary inside; per-row float2 layout
            float2 sacc = make_float2(0.f, 0.f);
            int scur = ida;
            int srun = 0;
            for (int r = rc; r < rc + CHUNK; ++r) {
                int id = __ldg(&image_id[r]);
                if (id != scur) {
                    atomicAdd(&g_sums[scur * N_DIM + lane * 2 + 0], sacc.x);
                    atomicAdd(&g_sums[scur * N_DIM + lane * 2 + 1], sacc.y);
                    if (lane == 0) atomicAdd(&g_counts[scur], srun);
                    sacc = make_float2(0.f, 0.f);
                    scur = id;
                    srun = 0;
                }
                float2 v = __ldcs(&x2[(size_t)r * (N_DIM / 2) + lane]);
                sacc.x += v.x;
                sacc.y += v.y;
                ++srun;
            }
            atomicAdd(&g_sums[scur * N_DIM + lane * 2 + 0], sacc.x);
            atomicAdd(&g_sums[scur * N_DIM + lane * 2 + 1], sacc.y);
            if (lane == 0) atomicAdd(&g_counts[scur], srun);
        }
    }
}

// ---------------------------------------------------------------------------
// finalize: averaged -> out[0:65536], counts -> tail; re-zero g_sums.
// ---------------------------------------------------------------------------
__global__ void finalize_kernel(float* __restrict__ out) {
    int tid = blockIdx.x * blockDim.x + threadIdx.x;
    if (tid < N_IMG * N_DIM) {
        int img = tid >> 6;  // /64
        int c = g_counts[img];
        float denom = (float)(c > 0 ? c : 1);
        out[tid] = g_sums[tid] / denom;
        g_sums[tid] = 0.0f;
    }
    if (tid < N_IMG) {
        out[N_IMG * N_DIM + N_ROWS + tid] = (float)g_counts[tid];
    }
}

// zero counts after finalize has consumed them (separate launch = ordering)
__global__ void zero_counts_kernel() {
    int tid = blockIdx.x * blockDim.x + threadIdx.x;
    if (tid < N_IMG) g_counts[tid] = 0;
}

// ---------------------------------------------------------------------------
extern "C" void kernel_launch(void* const* d_in, const int* in_sizes, int n_in,
                              void* d_out, int out_size) {
    const float* x = nullptr;
    const int* image_id = nullptr;
    for (int i = 0; i < n_in; ++i) {
        if (in_sizes[i] == N_ROWS * N_DIM) x = (const float*)d_in[i];
        else if (in_sizes[i] == N_ROWS)    image_id = (const int*)d_in[i];
    }
    float* out = (float*)d_out;

    main_kernel<<<BLOCKS, THREADS>>>(x, image_id, out);
    finalize_kernel<<<(N_IMG * N_DIM + 255) / 256, 256>>>(out);
    zero_counts_kernel<<<4, 256>>>();
}

// round 9
// speedup vs baseline: 1.6460x; 1.6460x over previous
#include <cuda_runtime.h>
#include <cuda_bf16.h>
#include <cstdint>

#define N_ROWS   4194304
#define N_DIM    64
#define N_IMG    1024

// scratch accumulators (no allocation allowed; zero-initialized at load,
// invariant: re-zeroed by finalize/zero_counts at the end of every launch)
__device__ float g_sums[N_IMG * N_DIM];
__device__ int   g_counts[N_IMG];

// exactly 4 blocks per SM on 148 SMs -> perfectly even single wave
#define BLOCKS   592
#define THREADS  256
#define WARPS_PER_BLOCK (THREADS / 32)
#define N_WARPS  (BLOCKS * WARPS_PER_BLOCK)      // 4736
#define CHUNK    128
#define N_CHUNKS (N_ROWS / CHUNK)                // 32768

__global__ __launch_bounds__(THREADS, 4)
void main_kernel(const float* __restrict__ x,
                 const int* __restrict__ image_id,
                 float* __restrict__ out) {
    // ---- fused id copy: grid-stride over 1M int4 (contiguous per iteration)
    {
        int tid = blockIdx.x * blockDim.x + threadIdx.x;
        const int4* src = reinterpret_cast<const int4*>(image_id);
        float4* dst = reinterpret_cast<float4*>(out + N_IMG * N_DIM);
        for (int i = tid; i < N_ROWS / 4; i += BLOCKS * THREADS) {
            int4 v = __ldcs(&src[i]);
            dst[i] = make_float4((float)v.x, (float)v.y, (float)v.z, (float)v.w);
        }
    }

    int gwarp = blockIdx.x * WARPS_PER_BLOCK + (threadIdx.x >> 5);
    int lane  = threadIdx.x & 31;
    int half  = lane >> 4;        // 0: even row of pair, 1: odd row
    int sub   = lane & 15;        // float4 slot (4 dims) within a row

    const float4* __restrict__ x4 = reinterpret_cast<const float4*>(x);
    const float2* __restrict__ x2 = reinterpret_cast<const float2*>(x);

    // CONTIGUOUS, evenly-split chunk range per warp: 6 or 7 chunks each
    int c_begin = (int)(((long long)gwarp       * N_CHUNKS) / N_WARPS);
    int c_end   = (int)(((long long)(gwarp + 1) * N_CHUNKS) / N_WARPS);

    for (int c = c_begin; c < c_end; ++c) {
        int rc  = c * CHUNK;
        int ida = __ldg(&image_id[rc]);
        int idb = __ldg(&image_id[rc + CHUNK - 1]);

        if (ida == idb) {
            // ---- fast chunk (~97%): uniform segment across 128 rows
            const float4* __restrict__ p =
                x4 + (size_t)(rc + half) * (N_DIM / 4) + sub;
            float4 a0 = make_float4(0.f, 0.f, 0.f, 0.f);
            float4 a1 = make_float4(0.f, 0.f, 0.f, 0.f);
            #pragma unroll 4
            for (int i = 0; i < CHUNK / 4; ++i) {
                float4 v0 = __ldcs(p + (size_t)(2 * i + 0) * (2 * N_DIM / 4));
                float4 v1 = __ldcs(p + (size_t)(2 * i + 1) * (2 * N_DIM / 4));
                a0.x += v0.x; a0.y += v0.y; a0.z += v0.z; a0.w += v0.w;
                a1.x += v1.x; a1.y += v1.y; a1.z += v1.z; a1.w += v1.w;
            }
            float4 t = make_float4(a0.x + a1.x, a0.y + a1.y,
                                   a0.z + a1.z, a0.w + a1.w);
            t.x += __shfl_down_sync(0xffffffff, t.x, 16);
            t.y += __shfl_down_sync(0xffffffff, t.y, 16);
            t.z += __shfl_down_sync(0xffffffff, t.z, 16);
            t.w += __shfl_down_sync(0xffffffff, t.w, 16);
            if (half == 0) {
                float* s = &g_sums[ida * N_DIM + sub * 4];
                atomicAdd(s + 0, t.x);
                atomicAdd(s + 1, t.y);
                atomicAdd(s + 2, t.z);
                atomicAdd(s + 3, t.w);
            }
            if (lane == 0) atomicAdd(&g_counts[ida], CHUNK);
        } else {
            // ---- slow chunk (~3%): boundary inside; per-row float2 layout
            float2 sacc = make_float2(0.f, 0.f);
            int scur = ida;
            int srun = 0;
            for (int r = rc; r < rc + CHUNK; ++r) {
                int id = __ldg(&image_id[r]);
                if (id != scur) {
                    atomicAdd(&g_sums[scur * N_DIM + lane * 2 + 0], sacc.x);
                    atomicAdd(&g_sums[scur * N_DIM + lane * 2 + 1], sacc.y);
                    if (lane == 0) atomicAdd(&g_counts[scur], srun);
                    sacc = make_float2(0.f, 0.f);
                    scur = id;
                    srun = 0;
                }
                float2 v = __ldcs(&x2[(size_t)r * (N_DIM / 2) + lane]);
                sacc.x += v.x;
                sacc.y += v.y;
                ++srun;
            }
            atomicAdd(&g_sums[scur * N_DIM + lane * 2 + 0], sacc.x);
            atomicAdd(&g_sums[scur * N_DIM + lane * 2 + 1], sacc.y);
            if (lane == 0) atomicAdd(&g_counts[scur], srun);
        }
    }
}

// ---------------------------------------------------------------------------
// finalize: averaged -> out[0:65536], counts -> tail; re-zero g_sums.
// ---------------------------------------------------------------------------
__global__ void finalize_kernel(float* __restrict__ out) {
    int tid = blockIdx.x * blockDim.x + threadIdx.x;
    if (tid < N_IMG * N_DIM) {
        int img = tid >> 6;  // /64
        int c = g_counts[img];
        float denom = (float)(c > 0 ? c : 1);
        out[tid] = g_sums[tid] / denom;
        g_sums[tid] = 0.0f;
    }
    if (tid < N_IMG) {
        out[N_IMG * N_DIM + N_ROWS + tid] = (float)g_counts[tid];
    }
}

// zero counts after finalize has consumed them (separate launch = ordering)
__global__ void zero_counts_kernel() {
    int tid = blockIdx.x * blockDim.x + threadIdx.x;
    if (tid < N_IMG) g_counts[tid] = 0;
}

// ---------------------------------------------------------------------------
extern "C" void kernel_launch(void* const* d_in, const int* in_sizes, int n_in,
                              void* d_out, int out_size) {
    const float* x = nullptr;
    const int* image_id = nullptr;
    for (int i = 0; i < n_in; ++i) {
        if (in_sizes[i] == N_ROWS * N_DIM) x = (const float*)d_in[i];
        else if (in_sizes[i] == N_ROWS)    image_id = (const int*)d_in[i];
    }
    float* out = (float*)d_out;

    main_kernel<<<BLOCKS, THREADS>>>(x, image_id, out);
    finalize_kernel<<<(N_IMG * N_DIM + 255) / 256, 256>>>(out);
    zero_counts_kernel<<<4, 256>>>();
}

// round 10
// speedup vs baseline: 1.7354x; 1.0543x over previous
#include <cuda_runtime.h>
#include <cuda_bf16.h>
#include <cstdint>

#define N_ROWS   4194304
#define N_DIM    64
#define N_IMG    1024

__device__ float g_sums[N_IMG * N_DIM];
__device__ int   g_counts[N_IMG];

#define BLOCKS   592              // exactly 4 per SM on 148 SMs
#define THREADS  256
#define WARPS_PER_BLOCK (THREADS / 32)
#define N_WARPS  (BLOCKS * WARPS_PER_BLOCK)      // 4736
#define CHUNK    128
#define N_CHUNKS (N_ROWS / CHUNK)                // 32768

#define STAGE_ROWS  8
#define STAGE_FLOATS (STAGE_ROWS * N_DIM)        // 512 floats
#define STAGE_BYTES (STAGE_FLOATS * 4)           // 2048
#define DEPTH 2

// ---------------- PTX helpers ----------------
__device__ __forceinline__ unsigned smem_u32(const void* p) {
    return (unsigned)__cvta_generic_to_shared(p);
}
__device__ __forceinline__ void mbar_init(unsigned a) {
    asm volatile("mbarrier.init.shared.b64 [%0], 1;" :: "r"(a) : "memory");
}
__device__ __forceinline__ void mbar_expect_tx(unsigned a, unsigned bytes) {
    asm volatile("mbarrier.arrive.expect_tx.shared.b64 _, [%0], %1;"
                 :: "r"(a), "r"(bytes) : "memory");
}
__device__ __forceinline__ void bulk_load(unsigned dst, const void* src,
                                          unsigned bytes, unsigned mbar) {
    asm volatile(
        "cp.async.bulk.shared::cluster.global.mbarrier::complete_tx::bytes "
        "[%0], [%1], %2, [%3];"
        :: "r"(dst), "l"(src), "r"(bytes), "r"(mbar) : "memory");
}
__device__ __forceinline__ void mbar_wait(unsigned a, unsigned phase) {
    asm volatile(
        "{\n\t"
        ".reg .pred P;\n\t"
        "WLP_%=:\n\t"
        "mbarrier.try_wait.parity.acquire.cta.shared::cta.b64 P, [%0], %1, 0x989680;\n\t"
        "@P bra.uni WDN_%=;\n\t"
        "bra.uni WLP_%=;\n\t"
        "WDN_%=:\n\t"
        "}"
        :: "r"(a), "r"(phase) : "memory");
}

__global__ __launch_bounds__(THREADS, 4)
void main_kernel(const float* __restrict__ x,
                 const int* __restrict__ image_id,
                 float* __restrict__ out) {
    __shared__ __align__(16) float stage_buf[WARPS_PER_BLOCK][DEPTH][STAGE_FLOATS];
    __shared__ __align__(8) unsigned long long stage_mbar[WARPS_PER_BLOCK][DEPTH];

    int wid  = threadIdx.x >> 5;
    int lane = threadIdx.x & 31;

    if (lane == 0) {
        mbar_init(smem_u32(&stage_mbar[wid][0]));
        mbar_init(smem_u32(&stage_mbar[wid][1]));
    }
    __syncwarp();

    // ---- fused id copy: grid-stride over 1M int4
    {
        int tid = blockIdx.x * blockDim.x + threadIdx.x;
        const int4* src = reinterpret_cast<const int4*>(image_id);
        float4* dst = reinterpret_cast<float4*>(out + N_IMG * N_DIM);
        for (int i = tid; i < N_ROWS / 4; i += BLOCKS * THREADS) {
            int4 v = __ldcs(&src[i]);
            dst[i] = make_float4((float)v.x, (float)v.y, (float)v.z, (float)v.w);
        }
    }

    int gwarp = blockIdx.x * WARPS_PER_BLOCK + wid;
    int half  = lane >> 4;        // 0: even row of pair, 1: odd row
    int sub   = lane & 15;        // float4 slot (4 dims) within a row

    // contiguous, evenly-split chunk range per warp
    int c_begin = (int)(((long long)gwarp       * N_CHUNKS) / N_WARPS);
    int c_end   = (int)(((long long)(gwarp + 1) * N_CHUNKS) / N_WARPS);
    int r0 = c_begin * CHUNK;
    int r1 = c_end   * CHUNK;
    int nstages = (r1 - r0) / STAGE_ROWS;

    unsigned mb[2] = { smem_u32(&stage_mbar[wid][0]), smem_u32(&stage_mbar[wid][1]) };
    unsigned db[2] = { smem_u32(&stage_buf[wid][0][0]), smem_u32(&stage_buf[wid][1][0]) };
    int phase[2] = {0, 0};

    // prologue: fill both buffers
    if (lane == 0) {
        #pragma unroll
        for (int s = 0; s < DEPTH; ++s) {
            mbar_expect_tx(mb[s], STAGE_BYTES);
            bulk_load(db[s], x + (size_t)(r0 + s * STAGE_ROWS) * N_DIM,
                      STAGE_BYTES, mb[s]);
        }
    }

    float4 acc = make_float4(0.f, 0.f, 0.f, 0.f);
    int cur = -1;
    int runlen = 0;

    #define FLUSH()                                                          \
        do {                                                                 \
            if (runlen > 0) {                                                \
                float4 t = acc;                                              \
                t.x += __shfl_down_sync(0xffffffff, t.x, 16);                \
                t.y += __shfl_down_sync(0xffffffff, t.y, 16);                \
                t.z += __shfl_down_sync(0xffffffff, t.z, 16);                \
                t.w += __shfl_down_sync(0xffffffff, t.w, 16);                \
                if (half == 0) {                                             \
                    float* s_ = &g_sums[cur * N_DIM + sub * 4];              \
                    atomicAdd(s_ + 0, t.x);                                  \
                    atomicAdd(s_ + 1, t.y);                                  \
                    atomicAdd(s_ + 2, t.z);                                  \
                    atomicAdd(s_ + 3, t.w);                                  \
                }                                                            \
                if (lane == 0) atomicAdd(&g_counts[cur], runlen);            \
                acc = make_float4(0.f, 0.f, 0.f, 0.f);                       \
                runlen = 0;                                                  \
            }                                                                \
        } while (0)

    for (int s = 0; s < nstages; ++s) {
        int buf = s & 1;
        mbar_wait(mb[buf], phase[buf]);
        phase[buf] ^= 1;

        int sr = r0 + s * STAGE_ROWS;
        int ida = __ldg(&image_id[sr]);
        int idb = __ldg(&image_id[sr + STAGE_ROWS - 1]);

        if (ida == idb) {
            // fast stage: uniform segment across its 8 rows
            if (ida != cur) { FLUSH(); cur = ida; }
            const float4* sp = reinterpret_cast<const float4*>(&stage_buf[wid][buf][0]);
            #pragma unroll
            for (int j = 0; j < STAGE_ROWS / 2; ++j) {
                float4 v = sp[(2 * j + half) * (N_DIM / 4) + sub];
                acc.x += v.x; acc.y += v.y; acc.z += v.z; acc.w += v.w;
            }
            runlen += STAGE_ROWS;
        } else {
            // slow stage: boundary inside; per-row float2 from smem
            FLUSH();
            const float2* sp2 = reinterpret_cast<const float2*>(&stage_buf[wid][buf][0]);
            float2 sacc = make_float2(0.f, 0.f);
            int scur = ida;
            int srun = 0;
            #pragma unroll
            for (int r = 0; r < STAGE_ROWS; ++r) {
                int id = __ldg(&image_id[sr + r]);
                if (id != scur) {
                    atomicAdd(&g_sums[scur * N_DIM + lane * 2 + 0], sacc.x);
                    atomicAdd(&g_sums[scur * N_DIM + lane * 2 + 1], sacc.y);
                    if (lane == 0) atomicAdd(&g_counts[scur], srun);
                    sacc = make_float2(0.f, 0.f);
                    scur = id;
                    srun = 0;
                }
                float2 v = sp2[r * (N_DIM / 2) + lane];
                sacc.x += v.x;
                sacc.y += v.y;
                ++srun;
            }
            atomicAdd(&g_sums[scur * N_DIM + lane * 2 + 0], sacc.x);
            atomicAdd(&g_sums[scur * N_DIM + lane * 2 + 1], sacc.y);
            if (lane == 0) atomicAdd(&g_counts[scur], srun);
            cur = -1;
        }

        // refill this buffer with stage s+DEPTH (consumption is complete:
        // the FADDs above consumed the LDS results, so smem reads are done
        // before this issue in warp program order)
        int ns = s + DEPTH;
        if (ns < nstages && lane == 0) {
            mbar_expect_tx(mb[buf], STAGE_BYTES);
            bulk_load(db[buf], x + (size_t)(r0 + ns * STAGE_ROWS) * N_DIM,
                      STAGE_BYTES, mb[buf]);
        }
    }
    FLUSH();
    #undef FLUSH
}

// ---------------------------------------------------------------------------
__global__ void finalize_kernel(float* __restrict__ out) {
    int tid = blockIdx.x * blockDim.x + threadIdx.x;
    if (tid < N_IMG * N_DIM) {
        int img = tid >> 6;
        int c = g_counts[img];
        float denom = (float)(c > 0 ? c : 1);
        out[tid] = g_sums[tid] / denom;
        g_sums[tid] = 0.0f;
    }
    if (tid < N_IMG) {
        out[N_IMG * N_DIM + N_ROWS + tid] = (float)g_counts[tid];
    }
}

__global__ void zero_counts_kernel() {
    int tid = blockIdx.x * blockDim.x + threadIdx.x;
    if (tid < N_IMG) g_counts[tid] = 0;
}

// ---------------------------------------------------------------------------
extern "C" void kernel_launch(void* const* d_in, const int* in_sizes, int n_in,
                              void* d_out, int out_size) {
    const float* x = nullptr;
    const int* image_id = nullptr;
    for (int i = 0; i < n_in; ++i) {
        if (in_sizes[i] == N_ROWS * N_DIM) x = (const float*)d_in[i];
        else if (in_sizes[i] == N_ROWS)    image_id = (const int*)d_in[i];
    }
    float* out = (float*)d_out;

    main_kernel<<<BLOCKS, THREADS>>>(x, image_id, out);
    finalize_kernel<<<(N_IMG * N_DIM + 255) / 256, 256>>>(out);
    zero_counts_kernel<<<4, 256>>>();
}

// round 11
// speedup vs baseline: 1.7702x; 1.0201x over previous
#include <cuda_runtime.h>
#include <cuda_bf16.h>
#include <cstdint>

#define N_ROWS   4194304
#define N_DIM    64
#define N_IMG    1024

__device__ float g_sums[N_IMG * N_DIM];
__device__ int   g_counts[N_IMG];

#define BLOCKS   592              // exactly 4 per SM on 148 SMs
#define THREADS  256
#define WARPS_PER_BLOCK (THREADS / 32)
#define N_WARPS  (BLOCKS * WARPS_PER_BLOCK)      // 4736
#define CHUNK    128
#define N_CHUNKS (N_ROWS / CHUNK)                // 32768

#define STAGE_ROWS  8
#define STAGE_FLOATS (STAGE_ROWS * N_DIM)        // 512 floats
#define STAGE_BYTES (STAGE_FLOATS * 4)           // 2048
#define DEPTH 3
#define DYN_SMEM (WARPS_PER_BLOCK * DEPTH * STAGE_BYTES)   // 49152

// ---------------- PTX helpers ----------------
__device__ __forceinline__ unsigned smem_u32(const void* p) {
    return (unsigned)__cvta_generic_to_shared(p);
}
__device__ __forceinline__ void mbar_init(unsigned a) {
    asm volatile("mbarrier.init.shared.b64 [%0], 1;" :: "r"(a) : "memory");
}
__device__ __forceinline__ void mbar_expect_tx(unsigned a, unsigned bytes) {
    asm volatile("mbarrier.arrive.expect_tx.shared.b64 _, [%0], %1;"
                 :: "r"(a), "r"(bytes) : "memory");
}
__device__ __forceinline__ void bulk_load(unsigned dst, const void* src,
                                          unsigned bytes, unsigned mbar) {
    asm volatile(
        "cp.async.bulk.shared::cluster.global.mbarrier::complete_tx::bytes "
        "[%0], [%1], %2, [%3];"
        :: "r"(dst), "l"(src), "r"(bytes), "r"(mbar) : "memory");
}
__device__ __forceinline__ void mbar_wait(unsigned a, unsigned phase) {
    asm volatile(
        "{\n\t"
        ".reg .pred P;\n\t"
        "WLP_%=:\n\t"
        "mbarrier.try_wait.parity.acquire.cta.shared::cta.b64 P, [%0], %1, 0x989680;\n\t"
        "@P bra.uni WDN_%=;\n\t"
        "bra.uni WLP_%=;\n\t"
        "WDN_%=:\n\t"
        "}"
        :: "r"(a), "r"(phase) : "memory");
}

__global__ __launch_bounds__(THREADS, 4)
void main_kernel(const float* __restrict__ x,
                 const int* __restrict__ image_id,
                 float* __restrict__ out) {
    extern __shared__ __align__(16) float dyn_smem[];
    __shared__ __align__(8) unsigned long long stage_mbar[WARPS_PER_BLOCK][DEPTH];

    int wid  = threadIdx.x >> 5;
    int lane = threadIdx.x & 31;

    // per-warp stage buffers in dynamic smem
    float* my_stages = dyn_smem + (size_t)wid * DEPTH * STAGE_FLOATS;

    if (lane < DEPTH) {
        mbar_init(smem_u32(&stage_mbar[wid][lane]));
    }
    __syncwarp();

    // ---- fused id copy: grid-stride over 1M int4
    {
        int tid = blockIdx.x * blockDim.x + threadIdx.x;
        const int4* src = reinterpret_cast<const int4*>(image_id);
        float4* dst = reinterpret_cast<float4*>(out + N_IMG * N_DIM);
        for (int i = tid; i < N_ROWS / 4; i += BLOCKS * THREADS) {
            int4 v = __ldcs(&src[i]);
            dst[i] = make_float4((float)v.x, (float)v.y, (float)v.z, (float)v.w);
        }
    }

    int gwarp = blockIdx.x * WARPS_PER_BLOCK + wid;
    int half  = lane >> 4;        // 0: even row of pair, 1: odd row
    int sub   = lane & 15;        // float4 slot (4 dims) within a row

    // contiguous, evenly-split chunk range per warp
    int c_begin = (int)(((long long)gwarp       * N_CHUNKS) / N_WARPS);
    int c_end   = (int)(((long long)(gwarp + 1) * N_CHUNKS) / N_WARPS);
    int r0 = c_begin * CHUNK;
    int r1 = c_end   * CHUNK;
    int nstages = (r1 - r0) / STAGE_ROWS;

    unsigned mb[DEPTH];
    unsigned db[DEPTH];
    int phase[DEPTH];
    #pragma unroll
    for (int s = 0; s < DEPTH; ++s) {
        mb[s] = smem_u32(&stage_mbar[wid][s]);
        db[s] = smem_u32(my_stages + s * STAGE_FLOATS);
        phase[s] = 0;
    }

    // prologue: fill all DEPTH buffers
    if (lane == 0) {
        #pragma unroll
        for (int s = 0; s < DEPTH; ++s) {
            mbar_expect_tx(mb[s], STAGE_BYTES);
            bulk_load(db[s], x + (size_t)(r0 + s * STAGE_ROWS) * N_DIM,
                      STAGE_BYTES, mb[s]);
        }
    }

    float4 acc = make_float4(0.f, 0.f, 0.f, 0.f);
    int cur = -1;
    int runlen = 0;

    #define FLUSH()                                                          \
        do {                                                                 \
            if (runlen > 0) {                                                \
                float4 t = acc;                                              \
                t.x += __shfl_down_sync(0xffffffff, t.x, 16);                \
                t.y += __shfl_down_sync(0xffffffff, t.y, 16);                \
                t.z += __shfl_down_sync(0xffffffff, t.z, 16);                \
                t.w += __shfl_down_sync(0xffffffff, t.w, 16);                \
                if (half == 0) {                                             \
                    float* s_ = &g_sums[cur * N_DIM + sub * 4];              \
                    atomicAdd(s_ + 0, t.x);                                  \
                    atomicAdd(s_ + 1, t.y);                                  \
                    atomicAdd(s_ + 2, t.z);                                  \
                    atomicAdd(s_ + 3, t.w);                                  \
                }                                                            \
                if (lane == 0) atomicAdd(&g_counts[cur], runlen);            \
                acc = make_float4(0.f, 0.f, 0.f, 0.f);                       \
                runlen = 0;                                                  \
            }                                                                \
        } while (0)

    int buf = 0;
    for (int s = 0; s < nstages; ++s) {
        mbar_wait(mb[buf], phase[buf]);
        phase[buf] ^= 1;

        int sr = r0 + s * STAGE_ROWS;
        int ida = __ldg(&image_id[sr]);
        int idb = __ldg(&image_id[sr + STAGE_ROWS - 1]);
        const float* sbase = my_stages + buf * STAGE_FLOATS;

        if (ida == idb) {
            // fast stage: uniform segment across its 8 rows
            if (ida != cur) { FLUSH(); cur = ida; }
            const float4* sp = reinterpret_cast<const float4*>(sbase);
            #pragma unroll
            for (int j = 0; j < STAGE_ROWS / 2; ++j) {
                float4 v = sp[(2 * j + half) * (N_DIM / 4) + sub];
                acc.x += v.x; acc.y += v.y; acc.z += v.z; acc.w += v.w;
            }
            runlen += STAGE_ROWS;
        } else {
            // slow stage: boundary inside; per-row float2 from smem
            FLUSH();
            const float2* sp2 = reinterpret_cast<const float2*>(sbase);
            float2 sacc = make_float2(0.f, 0.f);
            int scur = ida;
            int srun = 0;
            #pragma unroll
            for (int r = 0; r < STAGE_ROWS; ++r) {
                int id = __ldg(&image_id[sr + r]);
                if (id != scur) {
                    atomicAdd(&g_sums[scur * N_DIM + lane * 2 + 0], sacc.x);
                    atomicAdd(&g_sums[scur * N_DIM + lane * 2 + 1], sacc.y);
                    if (lane == 0) atomicAdd(&g_counts[scur], srun);
                    sacc = make_float2(0.f, 0.f);
                    scur = id;
                    srun = 0;
                }
                float2 v = sp2[r * (N_DIM / 2) + lane];
                sacc.x += v.x;
                sacc.y += v.y;
                ++srun;
            }
            atomicAdd(&g_sums[scur * N_DIM + lane * 2 + 0], sacc.x);
            atomicAdd(&g_sums[scur * N_DIM + lane * 2 + 1], sacc.y);
            if (lane == 0) atomicAdd(&g_counts[scur], srun);
            cur = -1;
        }

        // refill this buffer with stage s+DEPTH (smem reads above are
        // complete in warp program order before this issue)
        int ns = s + DEPTH;
        if (ns < nstages && lane == 0) {
            mbar_expect_tx(mb[buf], STAGE_BYTES);
            bulk_load(db[buf], x + (size_t)(r0 + ns * STAGE_ROWS) * N_DIM,
                      STAGE_BYTES, mb[buf]);
        }
        buf = (buf + 1 == DEPTH) ? 0 : buf + 1;
    }
    FLUSH();
    #undef FLUSH
}

// ---------------------------------------------------------------------------
__global__ void finalize_kernel(float* __restrict__ out) {
    int tid = blockIdx.x * blockDim.x + threadIdx.x;
    if (tid < N_IMG * N_DIM) {
        int img = tid >> 6;
        int c = g_counts[img];
        float denom = (float)(c > 0 ? c : 1);
        out[tid] = g_sums[tid] / denom;
        g_sums[tid] = 0.0f;
    }
    if (tid < N_IMG) {
        out[N_IMG * N_DIM + N_ROWS + tid] = (float)g_counts[tid];
    }
}

__global__ void zero_counts_kernel() {
    int tid = blockIdx.x * blockDim.x + threadIdx.x;
    if (tid < N_IMG) g_counts[tid] = 0;
}

// ---------------------------------------------------------------------------
extern "C" void kernel_launch(void* const* d_in, const int* in_sizes, int n_in,
                              void* d_out, int out_size) {
    const float* x = nullptr;
    const int* image_id = nullptr;
    for (int i = 0; i < n_in; ++i) {
        if (in_sizes[i] == N_ROWS * N_DIM) x = (const float*)d_in[i];
        else if (in_sizes[i] == N_ROWS)    image_id = (const int*)d_in[i];
    }
    float* out = (float*)d_out;

    // raise dynamic smem cap (idempotent; not an allocation, not a graph op)
    static bool attr_set = false;
    if (!attr_set) {
        cudaFuncSetAttribute(main_kernel,
                             cudaFuncAttributeMaxDynamicSharedMemorySize,
                             DYN_SMEM);
        attr_set = true;
    }

    main_kernel<<<BLOCKS, THREADS, DYN_SMEM>>>(x, image_id, out);
    finalize_kernel<<<(N_IMG * N_DIM + 255) / 256, 256>>>(out);
    zero_counts_kernel<<<4, 256>>>();
}

// round 12
// speedup vs baseline: 1.7831x; 1.0073x over previous
#include <cuda_runtime.h>
#include <cuda_bf16.h>
#include <cstdint>

#define N_ROWS   4194304
#define N_DIM    64
#define N_IMG    1024

__device__ float g_sums[N_IMG * N_DIM];
__device__ int   g_counts[N_IMG];

#define BLOCKS   592              // exactly 4 per SM on 148 SMs
#define THREADS  256
#define WARPS_PER_BLOCK (THREADS / 32)
#define N_WARPS  (BLOCKS * WARPS_PER_BLOCK)      // 4736

#define STAGE_ROWS  8
#define STAGE_FLOATS (STAGE_ROWS * N_DIM)        // 512 floats
#define STAGE_BYTES (STAGE_FLOATS * 4)           // 2048
#define DEPTH 3
#define DYN_SMEM (WARPS_PER_BLOCK * DEPTH * STAGE_BYTES)   // 49152
#define TOTAL_STAGES (N_ROWS / STAGE_ROWS)       // 524288

// ---------------- PTX helpers ----------------
__device__ __forceinline__ unsigned smem_u32(const void* p) {
    return (unsigned)__cvta_generic_to_shared(p);
}
__device__ __forceinline__ void mbar_init(unsigned a) {
    asm volatile("mbarrier.init.shared.b64 [%0], 1;" :: "r"(a) : "memory");
}
__device__ __forceinline__ void mbar_expect_tx(unsigned a, unsigned bytes) {
    asm volatile("mbarrier.arrive.expect_tx.shared.b64 _, [%0], %1;"
                 :: "r"(a), "r"(bytes) : "memory");
}
__device__ __forceinline__ void bulk_load(unsigned dst, const void* src,
                                          unsigned bytes, unsigned mbar) {
    asm volatile(
        "cp.async.bulk.shared::cluster.global.mbarrier::complete_tx::bytes "
        "[%0], [%1], %2, [%3];"
        :: "r"(dst), "l"(src), "r"(bytes), "r"(mbar) : "memory");
}
__device__ __forceinline__ void mbar_wait(unsigned a, unsigned phase) {
    asm volatile(
        "{\n\t"
        ".reg .pred P;\n\t"
        "WLP_%=:\n\t"
        "mbarrier.try_wait.parity.acquire.cta.shared::cta.b64 P, [%0], %1, 0x989680;\n\t"
        "@P bra.uni WDN_%=;\n\t"
        "bra.uni WLP_%=;\n\t"
        "WDN_%=:\n\t"
        "}"
        :: "r"(a), "r"(phase) : "memory");
}

__global__ __launch_bounds__(THREADS, 4)
void main_kernel(const float* __restrict__ x,
                 const int* __restrict__ image_id,
                 float* __restrict__ out) {
    extern __shared__ __align__(16) float dyn_smem[];
    __shared__ __align__(8) unsigned long long stage_mbar[WARPS_PER_BLOCK][DEPTH];

    int wid  = threadIdx.x >> 5;
    int lane = threadIdx.x & 31;

    float* my_stages = dyn_smem + (size_t)wid * DEPTH * STAGE_FLOATS;

    if (lane < DEPTH) {
        mbar_init(smem_u32(&stage_mbar[wid][lane]));
    }
    __syncwarp();

    // ---- fused id copy: grid-stride over 1M int4
    {
        int tid = blockIdx.x * blockDim.x + threadIdx.x;
        const int4* src = reinterpret_cast<const int4*>(image_id);
        float4* dst = reinterpret_cast<float4*>(out + N_IMG * N_DIM);
        for (int i = tid; i < N_ROWS / 4; i += BLOCKS * THREADS) {
            int4 v = __ldcs(&src[i]);
            dst[i] = make_float4((float)v.x, (float)v.y, (float)v.z, (float)v.w);
        }
    }

    int gwarp = blockIdx.x * WARPS_PER_BLOCK + wid;
    int half  = lane >> 4;        // 0: even row of pair, 1: odd row
    int sub   = lane & 15;        // float4 slot (4 dims) within a row

    // contiguous stage range per warp, 8-row granularity: 110 or 111 stages
    // (imbalance +-0.45% instead of +-7% at 128-row chunk granularity)
    int s_begin = (int)(((long long)gwarp       * TOTAL_STAGES) / N_WARPS);
    int s_end   = (int)(((long long)(gwarp + 1) * TOTAL_STAGES) / N_WARPS);
    int r0      = s_begin * STAGE_ROWS;
    int nstages = s_end - s_begin;

    unsigned mb[DEPTH];
    unsigned db[DEPTH];
    int phase[DEPTH];
    #pragma unroll
    for (int s = 0; s < DEPTH; ++s) {
        mb[s] = smem_u32(&stage_mbar[wid][s]);
        db[s] = smem_u32(my_stages + s * STAGE_FLOATS);
        phase[s] = 0;
    }

    // prologue: fill all DEPTH buffers
    if (lane == 0) {
        #pragma unroll
        for (int s = 0; s < DEPTH; ++s) {
            if (s < nstages) {
                mbar_expect_tx(mb[s], STAGE_BYTES);
                bulk_load(db[s], x + (size_t)(r0 + s * STAGE_ROWS) * N_DIM,
                          STAGE_BYTES, mb[s]);
            }
        }
    }

    float4 acc = make_float4(0.f, 0.f, 0.f, 0.f);
    int cur = -1;
    int runlen = 0;

    #define FLUSH()                                                          \
        do {                                                                 \
            if (runlen > 0) {                                                \
                float4 t = acc;                                              \
                t.x += __shfl_down_sync(0xffffffff, t.x, 16);                \
                t.y += __shfl_down_sync(0xffffffff, t.y, 16);                \
                t.z += __shfl_down_sync(0xffffffff, t.z, 16);                \
                t.w += __shfl_down_sync(0xffffffff, t.w, 16);                \
                if (half == 0) {                                             \
                    float* s_ = &g_sums[cur * N_DIM + sub * 4];              \
                    atomicAdd(s_ + 0, t.x);                                  \
                    atomicAdd(s_ + 1, t.y);                                  \
                    atomicAdd(s_ + 2, t.z);                                  \
                    atomicAdd(s_ + 3, t.w);                                  \
                }                                                            \
                if (lane == 0) atomicAdd(&g_counts[cur], runlen);            \
                acc = make_float4(0.f, 0.f, 0.f, 0.f);                       \
                runlen = 0;                                                  \
            }                                                                \
        } while (0)

    int buf = 0;
    for (int s = 0; s < nstages; ++s) {
        mbar_wait(mb[buf], phase[buf]);
        phase[buf] ^= 1;

        int sr = r0 + s * STAGE_ROWS;
        int ida = __ldg(&image_id[sr]);
        int idb = __ldg(&image_id[sr + STAGE_ROWS - 1]);
        const float* sbase = my_stages + buf * STAGE_FLOATS;

        if (ida == idb) {
            // fast stage: uniform segment across its 8 rows
            if (ida != cur) { FLUSH(); cur = ida; }
            const float4* sp = reinterpret_cast<const float4*>(sbase);
            #pragma unroll
            for (int j = 0; j < STAGE_ROWS / 2; ++j) {
                float4 v = sp[(2 * j + half) * (N_DIM / 4) + sub];
                acc.x += v.x; acc.y += v.y; acc.z += v.z; acc.w += v.w;
            }
            runlen += STAGE_ROWS;
        } else {
            // slow stage: boundary inside; per-row float2 from smem
            FLUSH();
            const float2* sp2 = reinterpret_cast<const float2*>(sbase);
            float2 sacc = make_float2(0.f, 0.f);
            int scur = ida;
            int srun = 0;
            #pragma unroll
            for (int r = 0; r < STAGE_ROWS; ++r) {
                int id = __ldg(&image_id[sr + r]);
                if (id != scur) {
                    atomicAdd(&g_sums[scur * N_DIM + lane * 2 + 0], sacc.x);
                    atomicAdd(&g_sums[scur * N_DIM + lane * 2 + 1], sacc.y);
                    if (lane == 0) atomicAdd(&g_counts[scur], srun);
                    sacc = make_float2(0.f, 0.f);
                    scur = id;
                    srun = 0;
                }
                float2 v = sp2[r * (N_DIM / 2) + lane];
                sacc.x += v.x;
                sacc.y += v.y;
                ++srun;
            }
            atomicAdd(&g_sums[scur * N_DIM + lane * 2 + 0], sacc.x);
            atomicAdd(&g_sums[scur * N_DIM + lane * 2 + 1], sacc.y);
            if (lane == 0) atomicAdd(&g_counts[scur], srun);
            cur = -1;
        }

        // refill this buffer with stage s+DEPTH
        int ns = s + DEPTH;
        if (ns < nstages && lane == 0) {
            mbar_expect_tx(mb[buf], STAGE_BYTES);
            bulk_load(db[buf], x + (size_t)(r0 + ns * STAGE_ROWS) * N_DIM,
                      STAGE_BYTES, mb[buf]);
        }
        buf = (buf + 1 == DEPTH) ? 0 : buf + 1;
    }
    FLUSH();
    #undef FLUSH
}

// ---------------------------------------------------------------------------
__global__ void finalize_kernel(float* __restrict__ out) {
    int tid = blockIdx.x * blockDim.x + threadIdx.x;
    if (tid < N_IMG * N_DIM) {
        int img = tid >> 6;
        int c = g_counts[img];
        float denom = (float)(c > 0 ? c : 1);
        out[tid] = g_sums[tid] / denom;
        g_sums[tid] = 0.0f;
    }
    if (tid < N_IMG) {
        out[N_IMG * N_DIM + N_ROWS + tid] = (float)g_counts[tid];
    }
}

__global__ void zero_counts_kernel() {
    int tid = blockIdx.x * blockDim.x + threadIdx.x;
    if (tid < N_IMG) g_counts[tid] = 0;
}

// ---------------------------------------------------------------------------
extern "C" void kernel_launch(void* const* d_in, const int* in_sizes, int n_in,
                              void* d_out, int out_size) {
    const float* x = nullptr;
    const int* image_id = nullptr;
    for (int i = 0; i < n_in; ++i) {
        if (in_sizes[i] == N_ROWS * N_DIM) x = (const float*)d_in[i];
        else if (in_sizes[i] == N_ROWS)    image_id = (const int*)d_in[i];
    }
    float* out = (float*)d_out;

    static bool attr_set = false;
    if (!attr_set) {
        cudaFuncSetAttribute(main_kernel,
                             cudaFuncAttributeMaxDynamicSharedMemorySize,
                             DYN_SMEM);
        attr_set = true;
    }

    main_kernel<<<BLOCKS, THREADS, DYN_SMEM>>>(x, image_id, out);
    finalize_kernel<<<(N_IMG * N_DIM + 255) / 256, 256>>>(out);
    zero_counts_kernel<<<4, 256>>>();
}